// round 1
// baseline (speedup 1.0000x reference)
#include <cuda_runtime.h>
#include <cuda_bf16.h>

// Problem constants
#define BB  2
#define TT  2048
#define DD  1024
#define HH  16
#define HDV 64
#define D3  3072   // 3*D

// Scratch (allocation-free rule: __device__ globals)
__device__ float g_qkv[(size_t)BB * TT * D3];   // [B*T, 3D]  qkv projection
__device__ float g_vals[(size_t)BB * TT * DD];  // [B*T, D]   attn@V, t-major

// ---------------------------------------------------------------------------
// Generic NN GEMM with bias: C[M,N] = A[M,K] @ B[K,N] + bias[N]
// 128x128 block tile, BK=8, 256 threads, 8x8 per thread (split 4+4 to avoid
// smem bank conflicts). All dims must be multiples of 128 / 8 (they are).
// ---------------------------------------------------------------------------
__global__ void __launch_bounds__(256) gemm_bias_nn(
    const float* __restrict__ A, const float* __restrict__ Bm,
    const float* __restrict__ bias, float* __restrict__ C,
    int M, int N, int K)
{
    __shared__ float As[8][128];
    __shared__ float Bs[8][128];

    const int tid = threadIdx.x;
    const int tx  = tid & 15;
    const int ty  = tid >> 4;
    const int m0  = blockIdx.y * 128;
    const int n0  = blockIdx.x * 128;

    const int arow = tid >> 1;          // 0..127
    const int acol = (tid & 1) << 2;    // 0 or 4
    const int brow = tid >> 5;          // 0..7
    const int bcol = (tid & 31) << 2;   // 0..124

    const float* Ap = A + (size_t)(m0 + arow) * K + acol;
    const float* Bp = Bm + (size_t)brow * N + n0 + bcol;

    float acc[8][8];
#pragma unroll
    for (int i = 0; i < 8; i++)
#pragma unroll
        for (int j = 0; j < 8; j++) acc[i][j] = 0.f;

    for (int k0 = 0; k0 < K; k0 += 8) {
        float4 a4 = *reinterpret_cast<const float4*>(Ap);
        float4 b4 = *reinterpret_cast<const float4*>(Bp);
        As[acol + 0][arow] = a4.x;
        As[acol + 1][arow] = a4.y;
        As[acol + 2][arow] = a4.z;
        As[acol + 3][arow] = a4.w;
        *reinterpret_cast<float4*>(&Bs[brow][bcol]) = b4;
        __syncthreads();
#pragma unroll
        for (int kk = 0; kk < 8; kk++) {
            float ra[8], rb[8];
            *reinterpret_cast<float4*>(&ra[0]) = *reinterpret_cast<const float4*>(&As[kk][ty * 4]);
            *reinterpret_cast<float4*>(&ra[4]) = *reinterpret_cast<const float4*>(&As[kk][ty * 4 + 64]);
            *reinterpret_cast<float4*>(&rb[0]) = *reinterpret_cast<const float4*>(&Bs[kk][tx * 4]);
            *reinterpret_cast<float4*>(&rb[4]) = *reinterpret_cast<const float4*>(&Bs[kk][tx * 4 + 64]);
#pragma unroll
            for (int i = 0; i < 8; i++)
#pragma unroll
                for (int j = 0; j < 8; j++)
                    acc[i][j] = fmaf(ra[i], rb[j], acc[i][j]);
        }
        __syncthreads();
        Ap += 8;
        Bp += (size_t)8 * N;
    }

#pragma unroll
    for (int i = 0; i < 8; i++) {
        int m = m0 + ((i < 4) ? (ty * 4 + i) : (64 + ty * 4 + i - 4));
#pragma unroll
        for (int jh = 0; jh < 2; jh++) {
            int n = n0 + jh * 64 + tx * 4;
            float4 bb = *reinterpret_cast<const float4*>(&bias[n]);
            float4 o;
            o.x = acc[i][jh * 4 + 0] + bb.x;
            o.y = acc[i][jh * 4 + 1] + bb.y;
            o.z = acc[i][jh * 4 + 2] + bb.z;
            o.w = acc[i][jh * 4 + 3] + bb.w;
            *reinterpret_cast<float4*>(&C[(size_t)m * N + n]) = o;
        }
    }
}

// ---------------------------------------------------------------------------
// Scores: S[b,h,q,k] = scale * dot(Q[b,h,q,:], K[b,h,k,:]),  HD=64 (NT GEMM)
// Q/K live interleaved in g_qkv: row stride 3072, head h at col h*192 (+64 for K)
// ---------------------------------------------------------------------------
__global__ void __launch_bounds__(256) scores_kernel(float* __restrict__ attn)
{
    const int z = blockIdx.z;        // b*16 + h
    const int b = z >> 4;
    const int h = z & 15;
    const float* Qb = g_qkv + (size_t)b * TT * D3 + h * 192;
    const float* Kb = Qb + 64;
    float* S = attn + (size_t)z * TT * TT;

    __shared__ float As[8][128];
    __shared__ float Bs[8][128];

    const int tid = threadIdx.x;
    const int tx  = tid & 15;
    const int ty  = tid >> 4;
    const int m0  = blockIdx.y * 128;
    const int n0  = blockIdx.x * 128;
    const int arow = tid >> 1;
    const int acol = (tid & 1) << 2;

    const float* Ap = Qb + (size_t)(m0 + arow) * D3 + acol;
    const float* Bp = Kb + (size_t)(n0 + arow) * D3 + acol;

    float acc[8][8];
#pragma unroll
    for (int i = 0; i < 8; i++)
#pragma unroll
        for (int j = 0; j < 8; j++) acc[i][j] = 0.f;

#pragma unroll
    for (int k0 = 0; k0 < 64; k0 += 8) {
        float4 a4 = *reinterpret_cast<const float4*>(Ap + k0);
        float4 b4 = *reinterpret_cast<const float4*>(Bp + k0);
        As[acol + 0][arow] = a4.x;
        As[acol + 1][arow] = a4.y;
        As[acol + 2][arow] = a4.z;
        As[acol + 3][arow] = a4.w;
        Bs[acol + 0][arow] = b4.x;
        Bs[acol + 1][arow] = b4.y;
        Bs[acol + 2][arow] = b4.z;
        Bs[acol + 3][arow] = b4.w;
        __syncthreads();
#pragma unroll
        for (int kk = 0; kk < 8; kk++) {
            float ra[8], rb[8];
            *reinterpret_cast<float4*>(&ra[0]) = *reinterpret_cast<const float4*>(&As[kk][ty * 4]);
            *reinterpret_cast<float4*>(&ra[4]) = *reinterpret_cast<const float4*>(&As[kk][ty * 4 + 64]);
            *reinterpret_cast<float4*>(&rb[0]) = *reinterpret_cast<const float4*>(&Bs[kk][tx * 4]);
            *reinterpret_cast<float4*>(&rb[4]) = *reinterpret_cast<const float4*>(&Bs[kk][tx * 4 + 64]);
#pragma unroll
            for (int i = 0; i < 8; i++)
#pragma unroll
                for (int j = 0; j < 8; j++)
                    acc[i][j] = fmaf(ra[i], rb[j], acc[i][j]);
        }
        __syncthreads();
    }

    const float scale = 0.125f;  // 1/sqrt(64)
#pragma unroll
    for (int i = 0; i < 8; i++) {
        int m = m0 + ((i < 4) ? (ty * 4 + i) : (64 + ty * 4 + i - 4));
#pragma unroll
        for (int jh = 0; jh < 2; jh++) {
            int n = n0 + jh * 64 + tx * 4;
            float4 o;
            o.x = acc[i][jh * 4 + 0] * scale;
            o.y = acc[i][jh * 4 + 1] * scale;
            o.z = acc[i][jh * 4 + 2] * scale;
            o.w = acc[i][jh * 4 + 3] * scale;
            *reinterpret_cast<float4*>(&S[(size_t)m * TT + n]) = o;
        }
    }
}

// ---------------------------------------------------------------------------
// Row softmax over 2048 elements, in place. One block (256 thr) per row.
// ---------------------------------------------------------------------------
__global__ void __launch_bounds__(256) softmax_kernel(float* __restrict__ attn)
{
    float4* p = reinterpret_cast<float4*>(attn + (size_t)blockIdx.x * TT);
    const int tid = threadIdx.x;

    float4 v0 = p[tid];
    float4 v1 = p[tid + 256];

    float m = fmaxf(fmaxf(fmaxf(v0.x, v0.y), fmaxf(v0.z, v0.w)),
                    fmaxf(fmaxf(v1.x, v1.y), fmaxf(v1.z, v1.w)));

    __shared__ float red[8];
#pragma unroll
    for (int o = 16; o > 0; o >>= 1) m = fmaxf(m, __shfl_xor_sync(0xffffffffu, m, o));
    if ((tid & 31) == 0) red[tid >> 5] = m;
    __syncthreads();
    m = red[0];
#pragma unroll
    for (int i = 1; i < 8; i++) m = fmaxf(m, red[i]);
    __syncthreads();

    v0.x = __expf(v0.x - m); v0.y = __expf(v0.y - m);
    v0.z = __expf(v0.z - m); v0.w = __expf(v0.w - m);
    v1.x = __expf(v1.x - m); v1.y = __expf(v1.y - m);
    v1.z = __expf(v1.z - m); v1.w = __expf(v1.w - m);

    float s = v0.x + v0.y + v0.z + v0.w + v1.x + v1.y + v1.z + v1.w;
#pragma unroll
    for (int o = 16; o > 0; o >>= 1) s += __shfl_xor_sync(0xffffffffu, s, o);
    if ((tid & 31) == 0) red[tid >> 5] = s;
    __syncthreads();
    s = red[0];
#pragma unroll
    for (int i = 1; i < 8; i++) s += red[i];

    float inv = 1.0f / s;
    v0.x *= inv; v0.y *= inv; v0.z *= inv; v0.w *= inv;
    v1.x *= inv; v1.y *= inv; v1.z *= inv; v1.w *= inv;
    p[tid]       = v0;
    p[tid + 256] = v1;
}

// ---------------------------------------------------------------------------
// AV: vals[b, q, h*64+d] = sum_k attn[b,h,q,k] * V[b,h,k,d]
// Per (b,h): NN GEMM M=2048, N=64, K=2048. BM=128, BN=64, BK=16.
// ---------------------------------------------------------------------------
__global__ void __launch_bounds__(256) av_kernel(const float* __restrict__ attn)
{
    const int z = blockIdx.z;
    const int b = z >> 4;
    const int h = z & 15;
    const float* P  = attn + (size_t)z * TT * TT;                       // [2048,2048]
    const float* V  = g_qkv + (size_t)b * TT * D3 + h * 192 + 128;      // ld 3072
    float* Cb = g_vals + (size_t)b * TT * DD + h * HDV;                 // ld 1024

    __shared__ float As[16][128];
    __shared__ float Bs[16][64];

    const int tid = threadIdx.x;
    const int tx  = tid & 15;   // N: 16*4 = 64
    const int ty  = tid >> 4;   // M: 16*8 = 128 (split 4+4)
    const int m0  = blockIdx.y * 128;

    const int arow = tid >> 1;          // 0..127
    const int acol = (tid & 1) << 3;    // 0 or 8
    const int brow = tid >> 4;          // 0..15
    const int bcol = (tid & 15) << 2;   // 0..60

    float acc[8][4];
#pragma unroll
    for (int i = 0; i < 8; i++)
#pragma unroll
        for (int j = 0; j < 4; j++) acc[i][j] = 0.f;

    for (int k0 = 0; k0 < TT; k0 += 16) {
        float4 a0 = *reinterpret_cast<const float4*>(&P[(size_t)(m0 + arow) * TT + k0 + acol]);
        float4 a1 = *reinterpret_cast<const float4*>(&P[(size_t)(m0 + arow) * TT + k0 + acol + 4]);
        float4 b4 = *reinterpret_cast<const float4*>(&V[(size_t)(k0 + brow) * D3 + bcol]);
        As[acol + 0][arow] = a0.x; As[acol + 1][arow] = a0.y;
        As[acol + 2][arow] = a0.z; As[acol + 3][arow] = a0.w;
        As[acol + 4][arow] = a1.x; As[acol + 5][arow] = a1.y;
        As[acol + 6][arow] = a1.z; As[acol + 7][arow] = a1.w;
        *reinterpret_cast<float4*>(&Bs[brow][bcol]) = b4;
        __syncthreads();
#pragma unroll
        for (int kk = 0; kk < 16; kk++) {
            float ra[8], rb[4];
            *reinterpret_cast<float4*>(&ra[0]) = *reinterpret_cast<const float4*>(&As[kk][ty * 4]);
            *reinterpret_cast<float4*>(&ra[4]) = *reinterpret_cast<const float4*>(&As[kk][ty * 4 + 64]);
            *reinterpret_cast<float4*>(&rb[0]) = *reinterpret_cast<const float4*>(&Bs[kk][tx * 4]);
#pragma unroll
            for (int i = 0; i < 8; i++)
#pragma unroll
                for (int j = 0; j < 4; j++)
                    acc[i][j] = fmaf(ra[i], rb[j], acc[i][j]);
        }
        __syncthreads();
    }

#pragma unroll
    for (int i = 0; i < 8; i++) {
        int m = m0 + ((i < 4) ? (ty * 4 + i) : (64 + ty * 4 + i - 4));
        float4 o;
        o.x = acc[i][0]; o.y = acc[i][1]; o.z = acc[i][2]; o.w = acc[i][3];
        *reinterpret_cast<float4*>(&Cb[(size_t)m * DD + tx * 4]) = o;
    }
}

// ---------------------------------------------------------------------------
extern "C" void kernel_launch(void* const* d_in, const int* in_sizes, int n_in,
                              void* d_out, int out_size)
{
    const float* x      = (const float*)d_in[0];
    const float* W_qkv  = (const float*)d_in[1];
    const float* b_qkv  = (const float*)d_in[2];
    const float* W_out  = (const float*)d_in[3];
    const float* b_out  = (const float*)d_in[4];

    float* out  = (float*)d_out;
    float* attn = out + (size_t)BB * TT * DD;   // (out, attn) concatenated

    static float* qkv_s  = nullptr;
    static float* vals_s = nullptr;
    if (!qkv_s) {
        cudaGetSymbolAddress((void**)&qkv_s, g_qkv);
        cudaGetSymbolAddress((void**)&vals_s, g_vals);
    }

    // 1) QKV projection: [4096,1024] @ [1024,3072] + bias
    gemm_bias_nn<<<dim3(D3 / 128, (BB * TT) / 128), 256>>>(
        x, W_qkv, b_qkv, qkv_s, BB * TT, D3, DD);

    // 2) Scaled scores into attn region of d_out
    scores_kernel<<<dim3(TT / 128, TT / 128, BB * HH), 256>>>(attn);

    // 3) Row softmax in place
    softmax_kernel<<<dim3(BB * HH * TT), 256>>>(attn);

    // 4) attn @ V -> g_vals ([B*T, D], t-major)
    av_kernel<<<dim3(1, TT / 128, BB * HH), 256>>>(attn);

    // 5) Output projection: [4096,1024] @ [1024,1024] + bias
    gemm_bias_nn<<<dim3(DD / 128, (BB * TT) / 128), 256>>>(
        vals_s, W_out, b_out, out, BB * TT, DD, DD);
}

// round 2
// speedup vs baseline: 1.7796x; 1.7796x over previous
#include <cuda_runtime.h>
#include <cuda_bf16.h>
#include <cstdint>

// Problem constants
#define BB  2
#define TT  2048
#define DD  1024
#define HH  16
#define HDV 64
#define D3  3072   // 3*D

// Scratch (allocation-free rule: __device__ globals)
__device__ float g_qkv[(size_t)BB * TT * D3];   // [B*T, 3D]  qkv projection
__device__ float g_vals[(size_t)BB * TT * DD];  // [B*T, D]   attn@V, t-major

// ---------------------------------------------------------------------------
// tf32 helpers
// ---------------------------------------------------------------------------
__device__ __forceinline__ unsigned f2tf(float x) {
    unsigned r;
    asm("cvt.rna.tf32.f32 %0, %1;" : "=r"(r) : "f"(x));
    return r;
}

__device__ __forceinline__ void mma_tf32(float c[4],
                                         unsigned a0, unsigned a1, unsigned a2, unsigned a3,
                                         unsigned b0, unsigned b1) {
    asm volatile(
        "mma.sync.aligned.m16n8k8.row.col.f32.tf32.tf32.f32 "
        "{%0,%1,%2,%3}, {%4,%5,%6,%7}, {%8,%9}, {%0,%1,%2,%3};"
        : "+f"(c[0]), "+f"(c[1]), "+f"(c[2]), "+f"(c[3])
        : "r"(a0), "r"(a1), "r"(a2), "r"(a3), "r"(b0), "r"(b1));
}

// ---------------------------------------------------------------------------
// NN GEMM + bias, tf32 tensor cores.
// C[M,N] = A[M,K] @ B[K,N] + bias[N].  Block tile 128x128, BK=16, 256 thr.
// Warp grid 4(m) x 2(n); warp tile 32x64 -> mt=2 (m16), nt=8 (n8).
// ---------------------------------------------------------------------------
__global__ void __launch_bounds__(256) gemm_tf32_bias(
    const float* __restrict__ A, const float* __restrict__ Bm,
    const float* __restrict__ bias, float* __restrict__ C,
    int M, int N, int K)
{
    __shared__ __align__(16) unsigned As[128 * 20];   // [row][k], pad->stride 20
    __shared__ __align__(16) unsigned Bs[16 * 136];   // [k][n],  pad->stride 136

    const int tid = threadIdx.x;
    const int w   = tid >> 5;
    const int ln  = tid & 31;
    const int gid = ln >> 2;   // group id 0..7
    const int tig = ln & 3;    // thread-in-group 0..3
    const int wm  = (w & 3) * 32;
    const int wn  = (w >> 2) * 64;
    const int m0  = blockIdx.y * 128;
    const int n0  = blockIdx.x * 128;

    float acc[2][8][4];
#pragma unroll
    for (int i = 0; i < 2; i++)
#pragma unroll
        for (int j = 0; j < 8; j++)
#pragma unroll
            for (int t = 0; t < 4; t++) acc[i][j][t] = 0.f;

    for (int k0 = 0; k0 < K; k0 += 16) {
#pragma unroll
        for (int i = 0; i < 2; i++) {
            int lin  = tid + i * 256;
            int row  = lin >> 2;
            int c4   = (lin & 3) << 2;
            float4 a = *reinterpret_cast<const float4*>(&A[(size_t)(m0 + row) * K + k0 + c4]);
            uint4 ua = make_uint4(f2tf(a.x), f2tf(a.y), f2tf(a.z), f2tf(a.w));
            *reinterpret_cast<uint4*>(&As[row * 20 + c4]) = ua;

            int rowb = lin >> 5;
            int c4b  = (lin & 31) << 2;
            float4 b = *reinterpret_cast<const float4*>(&Bm[(size_t)(k0 + rowb) * N + n0 + c4b]);
            uint4 ub = make_uint4(f2tf(b.x), f2tf(b.y), f2tf(b.z), f2tf(b.w));
            *reinterpret_cast<uint4*>(&Bs[rowb * 136 + c4b]) = ub;
        }
        __syncthreads();

#pragma unroll
        for (int ks = 0; ks < 2; ks++) {
            unsigned af[2][4], bf[8][2];
#pragma unroll
            for (int mt = 0; mt < 2; mt++) {
                int base = (wm + mt * 16 + gid) * 20 + ks * 8 + tig;
                af[mt][0] = As[base];
                af[mt][1] = As[base + 8 * 20];
                af[mt][2] = As[base + 4];
                af[mt][3] = As[base + 8 * 20 + 4];
            }
#pragma unroll
            for (int nt = 0; nt < 8; nt++) {
                int base = (ks * 8 + tig) * 136 + wn + nt * 8 + gid;
                bf[nt][0] = Bs[base];
                bf[nt][1] = Bs[base + 4 * 136];
            }
#pragma unroll
            for (int mt = 0; mt < 2; mt++)
#pragma unroll
                for (int nt = 0; nt < 8; nt++)
                    mma_tf32(acc[mt][nt], af[mt][0], af[mt][1], af[mt][2], af[mt][3],
                             bf[nt][0], bf[nt][1]);
        }
        __syncthreads();
    }

#pragma unroll
    for (int mt = 0; mt < 2; mt++) {
#pragma unroll
        for (int nt = 0; nt < 8; nt++) {
            int n = n0 + wn + nt * 8 + 2 * tig;
            float2 bb = *reinterpret_cast<const float2*>(&bias[n]);
            int m = m0 + wm + mt * 16 + gid;
            float2 o0 = make_float2(acc[mt][nt][0] + bb.x, acc[mt][nt][1] + bb.y);
            float2 o1 = make_float2(acc[mt][nt][2] + bb.x, acc[mt][nt][3] + bb.y);
            *reinterpret_cast<float2*>(&C[(size_t)m * N + n])       = o0;
            *reinterpret_cast<float2*>(&C[(size_t)(m + 8) * N + n]) = o1;
        }
    }
}

// ---------------------------------------------------------------------------
// Scores (NT, tf32): S[b,h,q,k] = 0.125 * dot(Q[q,:64], K[k,:64])
// Q/K strided in g_qkv (row stride 3072). Block tile 128x128, K=64 (4x BK16).
// Both tiles stored [row][k] stride 20; B frag reads Bs[n][k].
// ---------------------------------------------------------------------------
__global__ void __launch_bounds__(256) scores_tf32(float* __restrict__ attn)
{
    const int z = blockIdx.z;
    const int b = z >> 4;
    const int h = z & 15;
    const float* Qb = g_qkv + (size_t)b * TT * D3 + h * 192;
    const float* Kb = Qb + 64;
    float* S = attn + (size_t)z * TT * TT;

    __shared__ __align__(16) unsigned As[128 * 20];
    __shared__ __align__(16) unsigned Bs[128 * 20];

    const int tid = threadIdx.x;
    const int w   = tid >> 5;
    const int ln  = tid & 31;
    const int gid = ln >> 2;
    const int tig = ln & 3;
    const int wm  = (w & 3) * 32;
    const int wn  = (w >> 2) * 64;
    const int m0  = blockIdx.y * 128;
    const int n0  = blockIdx.x * 128;

    float acc[2][8][4];
#pragma unroll
    for (int i = 0; i < 2; i++)
#pragma unroll
        for (int j = 0; j < 8; j++)
#pragma unroll
            for (int t = 0; t < 4; t++) acc[i][j][t] = 0.f;

#pragma unroll
    for (int k0 = 0; k0 < 64; k0 += 16) {
#pragma unroll
        for (int i = 0; i < 2; i++) {
            int lin = tid + i * 256;
            int row = lin >> 2;
            int c4  = (lin & 3) << 2;
            float4 a = *reinterpret_cast<const float4*>(&Qb[(size_t)(m0 + row) * D3 + k0 + c4]);
            *reinterpret_cast<uint4*>(&As[row * 20 + c4]) =
                make_uint4(f2tf(a.x), f2tf(a.y), f2tf(a.z), f2tf(a.w));
            float4 bq = *reinterpret_cast<const float4*>(&Kb[(size_t)(n0 + row) * D3 + k0 + c4]);
            *reinterpret_cast<uint4*>(&Bs[row * 20 + c4]) =
                make_uint4(f2tf(bq.x), f2tf(bq.y), f2tf(bq.z), f2tf(bq.w));
        }
        __syncthreads();

#pragma unroll
        for (int ks = 0; ks < 2; ks++) {
            unsigned af[2][4], bf[8][2];
#pragma unroll
            for (int mt = 0; mt < 2; mt++) {
                int base = (wm + mt * 16 + gid) * 20 + ks * 8 + tig;
                af[mt][0] = As[base];
                af[mt][1] = As[base + 8 * 20];
                af[mt][2] = As[base + 4];
                af[mt][3] = As[base + 8 * 20 + 4];
            }
#pragma unroll
            for (int nt = 0; nt < 8; nt++) {
                int base = (wn + nt * 8 + gid) * 20 + ks * 8 + tig;
                bf[nt][0] = Bs[base];
                bf[nt][1] = Bs[base + 4];
            }
#pragma unroll
            for (int mt = 0; mt < 2; mt++)
#pragma unroll
                for (int nt = 0; nt < 8; nt++)
                    mma_tf32(acc[mt][nt], af[mt][0], af[mt][1], af[mt][2], af[mt][3],
                             bf[nt][0], bf[nt][1]);
        }
        __syncthreads();
    }

    const float scale = 0.125f;
#pragma unroll
    for (int mt = 0; mt < 2; mt++) {
#pragma unroll
        for (int nt = 0; nt < 8; nt++) {
            int n = n0 + wn + nt * 8 + 2 * tig;
            int m = m0 + wm + mt * 16 + gid;
            float2 o0 = make_float2(acc[mt][nt][0] * scale, acc[mt][nt][1] * scale);
            float2 o1 = make_float2(acc[mt][nt][2] * scale, acc[mt][nt][3] * scale);
            *reinterpret_cast<float2*>(&S[(size_t)m * TT + n])       = o0;
            *reinterpret_cast<float2*>(&S[(size_t)(m + 8) * TT + n]) = o1;
        }
    }
}

// ---------------------------------------------------------------------------
// Row softmax over 2048 elements, in place. One block (256 thr) per row.
// ---------------------------------------------------------------------------
__global__ void __launch_bounds__(256) softmax_kernel(float* __restrict__ attn)
{
    float4* p = reinterpret_cast<float4*>(attn + (size_t)blockIdx.x * TT);
    const int tid = threadIdx.x;

    float4 v0 = p[tid];
    float4 v1 = p[tid + 256];

    float m = fmaxf(fmaxf(fmaxf(v0.x, v0.y), fmaxf(v0.z, v0.w)),
                    fmaxf(fmaxf(v1.x, v1.y), fmaxf(v1.z, v1.w)));

    __shared__ float red[8];
#pragma unroll
    for (int o = 16; o > 0; o >>= 1) m = fmaxf(m, __shfl_xor_sync(0xffffffffu, m, o));
    if ((tid & 31) == 0) red[tid >> 5] = m;
    __syncthreads();
    m = red[0];
#pragma unroll
    for (int i = 1; i < 8; i++) m = fmaxf(m, red[i]);
    __syncthreads();

    v0.x = __expf(v0.x - m); v0.y = __expf(v0.y - m);
    v0.z = __expf(v0.z - m); v0.w = __expf(v0.w - m);
    v1.x = __expf(v1.x - m); v1.y = __expf(v1.y - m);
    v1.z = __expf(v1.z - m); v1.w = __expf(v1.w - m);

    float s = v0.x + v0.y + v0.z + v0.w + v1.x + v1.y + v1.z + v1.w;
#pragma unroll
    for (int o = 16; o > 0; o >>= 1) s += __shfl_xor_sync(0xffffffffu, s, o);
    if ((tid & 31) == 0) red[tid >> 5] = s;
    __syncthreads();
    s = red[0];
#pragma unroll
    for (int i = 1; i < 8; i++) s += red[i];

    float inv = 1.0f / s;
    v0.x *= inv; v0.y *= inv; v0.z *= inv; v0.w *= inv;
    v1.x *= inv; v1.y *= inv; v1.z *= inv; v1.w *= inv;
    p[tid]       = v0;
    p[tid + 256] = v1;
}

// ---------------------------------------------------------------------------
// AV (NN, tf32): vals[b, q, h*64+d] = sum_k attn[b,h,q,k] * V[b,h,k,d]
// Per (b,h): M=2048, N=64, K=2048. Block 128x64, BK=16, 256 thr.
// Warp grid 4(m) x 2(n); warp tile 32x32 -> mt=2, nt=4.
// ---------------------------------------------------------------------------
__global__ void __launch_bounds__(256) av_tf32(const float* __restrict__ attn)
{
    const int z = blockIdx.z;
    const int b = z >> 4;
    const int h = z & 15;
    const float* P = attn + (size_t)z * TT * TT;
    const float* V = g_qkv + (size_t)b * TT * D3 + h * 192 + 128;  // ld 3072
    float* Cb = g_vals + (size_t)b * TT * DD + h * HDV;            // ld 1024

    __shared__ __align__(16) unsigned As[128 * 20];   // [m][k]
    __shared__ __align__(16) unsigned Bs[16 * 72];    // [k][n]

    const int tid = threadIdx.x;
    const int w   = tid >> 5;
    const int ln  = tid & 31;
    const int gid = ln >> 2;
    const int tig = ln & 3;
    const int wm  = (w & 3) * 32;
    const int wn  = (w >> 2) * 32;
    const int m0  = blockIdx.y * 128;

    float acc[2][4][4];
#pragma unroll
    for (int i = 0; i < 2; i++)
#pragma unroll
        for (int j = 0; j < 4; j++)
#pragma unroll
            for (int t = 0; t < 4; t++) acc[i][j][t] = 0.f;

    for (int k0 = 0; k0 < TT; k0 += 16) {
#pragma unroll
        for (int i = 0; i < 2; i++) {
            int lin = tid + i * 256;
            int row = lin >> 2;
            int c4  = (lin & 3) << 2;
            float4 a = *reinterpret_cast<const float4*>(&P[(size_t)(m0 + row) * TT + k0 + c4]);
            *reinterpret_cast<uint4*>(&As[row * 20 + c4]) =
                make_uint4(f2tf(a.x), f2tf(a.y), f2tf(a.z), f2tf(a.w));
        }
        {
            int row = tid >> 4;
            int c4  = (tid & 15) << 2;
            float4 bv = *reinterpret_cast<const float4*>(&V[(size_t)(k0 + row) * D3 + c4]);
            *reinterpret_cast<uint4*>(&Bs[row * 72 + c4]) =
                make_uint4(f2tf(bv.x), f2tf(bv.y), f2tf(bv.z), f2tf(bv.w));
        }
        __syncthreads();

#pragma unroll
        for (int ks = 0; ks < 2; ks++) {
            unsigned af[2][4], bf[4][2];
#pragma unroll
            for (int mt = 0; mt < 2; mt++) {
                int base = (wm + mt * 16 + gid) * 20 + ks * 8 + tig;
                af[mt][0] = As[base];
                af[mt][1] = As[base + 8 * 20];
                af[mt][2] = As[base + 4];
                af[mt][3] = As[base + 8 * 20 + 4];
            }
#pragma unroll
            for (int nt = 0; nt < 4; nt++) {
                int base = (ks * 8 + tig) * 72 + wn + nt * 8 + gid;
                bf[nt][0] = Bs[base];
                bf[nt][1] = Bs[base + 4 * 72];
            }
#pragma unroll
            for (int mt = 0; mt < 2; mt++)
#pragma unroll
                for (int nt = 0; nt < 4; nt++)
                    mma_tf32(acc[mt][nt], af[mt][0], af[mt][1], af[mt][2], af[mt][3],
                             bf[nt][0], bf[nt][1]);
        }
        __syncthreads();
    }

#pragma unroll
    for (int mt = 0; mt < 2; mt++) {
#pragma unroll
        for (int nt = 0; nt < 4; nt++) {
            int n = wn + nt * 8 + 2 * tig;
            int m = m0 + wm + mt * 16 + gid;
            float2 o0 = make_float2(acc[mt][nt][0], acc[mt][nt][1]);
            float2 o1 = make_float2(acc[mt][nt][2], acc[mt][nt][3]);
            *reinterpret_cast<float2*>(&Cb[(size_t)m * DD + n])       = o0;
            *reinterpret_cast<float2*>(&Cb[(size_t)(m + 8) * DD + n]) = o1;
        }
    }
}

// ---------------------------------------------------------------------------
extern "C" void kernel_launch(void* const* d_in, const int* in_sizes, int n_in,
                              void* d_out, int out_size)
{
    const float* x      = (const float*)d_in[0];
    const float* W_qkv  = (const float*)d_in[1];
    const float* b_qkv  = (const float*)d_in[2];
    const float* W_out  = (const float*)d_in[3];
    const float* b_out  = (const float*)d_in[4];

    float* out  = (float*)d_out;
    float* attn = out + (size_t)BB * TT * DD;   // (out, attn) concatenated

    static float* qkv_s  = nullptr;
    static float* vals_s = nullptr;
    if (!qkv_s) {
        cudaGetSymbolAddress((void**)&qkv_s, g_qkv);
        cudaGetSymbolAddress((void**)&vals_s, g_vals);
    }

    // 1) QKV projection: [4096,1024] @ [1024,3072] + bias -> g_qkv
    gemm_tf32_bias<<<dim3(D3 / 128, (BB * TT) / 128), 256>>>(
        x, W_qkv, b_qkv, qkv_s, BB * TT, D3, DD);

    // 2) Scaled scores into attn region of d_out
    scores_tf32<<<dim3(TT / 128, TT / 128, BB * HH), 256>>>(attn);

    // 3) Row softmax in place
    softmax_kernel<<<dim3(BB * HH * TT), 256>>>(attn);

    // 4) attn @ V -> g_vals ([B*T, D], t-major)
    av_tf32<<<dim3(1, TT / 128, BB * HH), 256>>>(attn);

    // 5) Output projection: [4096,1024] @ [1024,1024] + bias -> out
    gemm_tf32_bias<<<dim3(DD / 128, (BB * TT) / 128), 256>>>(
        vals_s, W_out, b_out, out, BB * TT, DD, DD);
}